// round 1
// baseline (speedup 1.0000x reference)
#include <cuda_runtime.h>
#include <math.h>

#define FULL_MASK 0xffffffffu
#define TWO_PI_F 6.28318530717958647692f

// Per-lane precomputed twiddle state for the warp-level 512-point FFT.
struct WarpTw {
    float twr[16], twi[16];      // w512^{lane * brev4(p)} for the four-step twiddle
    float s16, s8, s4, s2, s1;   // +1 on lower half-lanes, -1 on upper, per cross-lane stage
    float w16r, w16i;            // stage m=16 twiddle: upper lanes w32^{lane&15}, lower (1,0)
    float w8r, w8i;              // stage m=8:  w16^{lane&7}
    float w4r, w4i;              // stage m=4:  w8^{lane&3}
    float w2r, w2i;              // stage m=2:  w4^{lane&1}
};

__device__ __forceinline__ void cmul_ip(float& ar, float& ai, float wr, float wi) {
    float nr = ar * wr - ai * wi;
    float ni = ar * wi + ai * wr;
    ar = nr; ai = ni;
}

// 512-point complex FFT across one warp.
// Input: slot s of lane n2 holds x[32*s + n2].
// Output: a fixed (bit-reversed in both slot and lane) permutation of the DFT —
// identical permutation for every call, which is all the reduction needs.
__device__ __forceinline__ void fft512_warp(float (&xr)[16], float (&xi)[16], const WarpTw& W)
{
    // ---- per-thread 16-point DIF FFT over the 16 register slots ----
    {   // span 8, twiddles w16^j (compile-time constants -> FFMA-imm forms)
        const float WR[8] = {1.f, 0.9238795325f, 0.7071067812f, 0.3826834324f,
                             0.f, -0.3826834324f, -0.7071067812f, -0.9238795325f};
        const float WI[8] = {0.f, -0.3826834324f, -0.7071067812f, -0.9238795325f,
                             -1.f, -0.9238795325f, -0.7071067812f, -0.3826834324f};
        #pragma unroll
        for (int j = 0; j < 8; ++j) {
            float ur = xr[j] + xr[j+8], ui = xi[j] + xi[j+8];
            float vr = xr[j] - xr[j+8], vi = xi[j] - xi[j+8];
            xr[j] = ur; xi[j] = ui;
            xr[j+8] = vr * WR[j] - vi * WI[j];
            xi[j+8] = vr * WI[j] + vi * WR[j];
        }
    }
    {   // span 4, twiddles w8^j
        const float WR[4] = {1.f, 0.7071067812f, 0.f, -0.7071067812f};
        const float WI[4] = {0.f, -0.7071067812f, -1.f, -0.7071067812f};
        #pragma unroll
        for (int b = 0; b < 16; b += 8)
        #pragma unroll
        for (int j = 0; j < 4; ++j) {
            int p = b + j, q = p + 4;
            float ur = xr[p] + xr[q], ui = xi[p] + xi[q];
            float vr = xr[p] - xr[q], vi = xi[p] - xi[q];
            xr[p] = ur; xi[p] = ui;
            xr[q] = vr * WR[j] - vi * WI[j];
            xi[q] = vr * WI[j] + vi * WR[j];
        }
    }
    // span 2, twiddles {1, -i}
    #pragma unroll
    for (int b = 0; b < 16; b += 4) {
        {
            int p = b, q = b + 2;
            float ur = xr[p] + xr[q], ui = xi[p] + xi[q];
            float vr = xr[p] - xr[q], vi = xi[p] - xi[q];
            xr[p] = ur; xi[p] = ui; xr[q] = vr; xi[q] = vi;
        }
        {
            int p = b + 1, q = b + 3;
            float ur = xr[p] + xr[q], ui = xi[p] + xi[q];
            float vr = xr[p] - xr[q], vi = xi[p] - xi[q];
            xr[p] = ur; xi[p] = ui;
            xr[q] = vi; xi[q] = -vr;     // * (-i)
        }
    }
    // span 1, twiddle 1
    #pragma unroll
    for (int b = 0; b < 16; b += 2) {
        float ur = xr[b] + xr[b+1], ui = xi[b] + xi[b+1];
        float vr = xr[b] - xr[b+1], vi = xi[b] - xi[b+1];
        xr[b] = ur; xi[b] = ui; xr[b+1] = vr; xi[b+1] = vi;
    }

    // ---- four-step twiddle: slot p holds A[brev4(p)]; multiply by w512^{lane*brev4(p)} ----
    #pragma unroll
    for (int p = 1; p < 16; ++p)      // p=0 -> k1=0 -> twiddle is 1
        cmul_ip(xr[p], xi[p], W.twr[p], W.twi[p]);

    // ---- cross-lane 32-point DIF FFT per slot (shfl_xor butterflies) ----
    #pragma unroll
    for (int p = 0; p < 16; ++p) {
        float ar = xr[p], ai = xi[p];
        float pr, pi, ur, ui;

        pr = __shfl_xor_sync(FULL_MASK, ar, 16);
        pi = __shfl_xor_sync(FULL_MASK, ai, 16);
        ur = fmaf(W.s16, ar, pr); ui = fmaf(W.s16, ai, pi);
        ar = ur * W.w16r - ui * W.w16i;
        ai = ur * W.w16i + ui * W.w16r;

        pr = __shfl_xor_sync(FULL_MASK, ar, 8);
        pi = __shfl_xor_sync(FULL_MASK, ai, 8);
        ur = fmaf(W.s8, ar, pr); ui = fmaf(W.s8, ai, pi);
        ar = ur * W.w8r - ui * W.w8i;
        ai = ur * W.w8i + ui * W.w8r;

        pr = __shfl_xor_sync(FULL_MASK, ar, 4);
        pi = __shfl_xor_sync(FULL_MASK, ai, 4);
        ur = fmaf(W.s4, ar, pr); ui = fmaf(W.s4, ai, pi);
        ar = ur * W.w4r - ui * W.w4i;
        ai = ur * W.w4i + ui * W.w4r;

        pr = __shfl_xor_sync(FULL_MASK, ar, 2);
        pi = __shfl_xor_sync(FULL_MASK, ai, 2);
        ur = fmaf(W.s2, ar, pr); ui = fmaf(W.s2, ai, pi);
        ar = ur * W.w2r - ui * W.w2i;
        ai = ur * W.w2i + ui * W.w2r;

        pr = __shfl_xor_sync(FULL_MASK, ar, 1);
        pi = __shfl_xor_sync(FULL_MASK, ai, 1);
        ar = fmaf(W.s1, ar, pr);
        ai = fmaf(W.s1, ai, pi);

        xr[p] = ar; xi[p] = ai;
    }
}

// out[b] = Im( sum_f Z[f]^2 * conj(T[f]) ) / (2*D)
// with Z = FFT512(h + i*r), T = FFT512(t). One warp per row, grid-stride over rows.
__global__ void __launch_bounds__(128, 3)
hole_kernel(const float* __restrict__ h, const float* __restrict__ r,
            const float* __restrict__ t, float* __restrict__ out, int nrows)
{
    const int lane   = threadIdx.x & 31;
    const int warp   = blockIdx.x * (blockDim.x >> 5) + (threadIdx.x >> 5);
    const int nwarps = gridDim.x * (blockDim.x >> 5);

    // ---- one-time per-lane twiddle setup (amortized over ~8 rows/warp) ----
    WarpTw W;
    #pragma unroll
    for (int p = 0; p < 16; ++p) {
        int k1 = (int)(__brev((unsigned)p) >> 28);   // brev4(p)
        float ang = -(TWO_PI_F / 512.f) * (float)(lane * k1);
        sincosf(ang, &W.twi[p], &W.twr[p]);
    }
    W.s16 = (lane & 16) ? -1.f : 1.f;
    W.s8  = (lane & 8)  ? -1.f : 1.f;
    W.s4  = (lane & 4)  ? -1.f : 1.f;
    W.s2  = (lane & 2)  ? -1.f : 1.f;
    W.s1  = (lane & 1)  ? -1.f : 1.f;
    if (lane & 16) { float a = -(TWO_PI_F / 32.f) * (float)(lane & 15); sincosf(a, &W.w16i, &W.w16r); }
    else           { W.w16r = 1.f; W.w16i = 0.f; }
    if (lane & 8)  { float a = -(TWO_PI_F / 16.f) * (float)(lane & 7);  sincosf(a, &W.w8i, &W.w8r); }
    else           { W.w8r = 1.f; W.w8i = 0.f; }
    if (lane & 4)  { float a = -(TWO_PI_F / 8.f)  * (float)(lane & 3);  sincosf(a, &W.w4i, &W.w4r); }
    else           { W.w4r = 1.f; W.w4i = 0.f; }
    if (lane & 2)  { float a = -(TWO_PI_F / 4.f)  * (float)(lane & 1);  sincosf(a, &W.w2i, &W.w2r); }
    else           { W.w2r = 1.f; W.w2i = 0.f; }

    for (int row = warp; row < nrows; row += nwarps) {
        size_t base = (size_t)row * 512 + (size_t)lane;
        const float* hp = h + base;
        const float* rp = r + base;
        const float* tp = t + base;

        // coalesced loads: each of these is a full 128B warp transaction
        float zr[16], zi[16];
        #pragma unroll
        for (int s = 0; s < 16; ++s) { zr[s] = hp[32 * s]; zi[s] = rp[32 * s]; }
        float wr_[16], wi_[16];
        #pragma unroll
        for (int s = 0; s < 16; ++s) { wr_[s] = tp[32 * s]; wi_[s] = 0.f; }

        fft512_warp(zr, zi, W);     // Z = FFT(h + i r)
        fft512_warp(wr_, wi_, W);   // T = FFT(t)  (imag zeros fold at compile time)

        // acc = sum over this lane's 16 frequencies of Im(Z^2 * conj(T))
        float acc = 0.f;
        #pragma unroll
        for (int s = 0; s < 16; ++s) {
            float a = zr[s], b = zi[s];
            float im2 = 2.f * a * b;          // Im(Z^2)
            float re2 = a * a - b * b;        // Re(Z^2)
            acc = fmaf(im2, wr_[s], acc);
            acc = fmaf(-re2, wi_[s], acc);
        }
        #pragma unroll
        for (int o = 16; o; o >>= 1)
            acc += __shfl_xor_sync(FULL_MASK, acc, o);

        if (lane == 0) out[row] = acc * (1.f / 1024.f);   // 1/(2*D)
    }
}

extern "C" void kernel_launch(void* const* d_in, const int* in_sizes, int n_in,
                              void* d_out, int out_size)
{
    const float* h = (const float*)d_in[0];
    const float* r = (const float*)d_in[1];
    const float* t = (const float*)d_in[2];
    float* out = (float*)d_out;

    int nrows = in_sizes[0] / 512;      // 131072

    const int threads = 128;            // 4 warps/block
    const int blocks  = 4096;           // 16384 warps -> 8 rows per warp
    hole_kernel<<<blocks, threads>>>(h, r, t, out, nrows);
}

// round 2
// speedup vs baseline: 1.1451x; 1.1451x over previous
#include <cuda_runtime.h>
#include <math.h>

#define FULL_MASK 0xffffffffu
#define TWO_PI_F 6.28318530717958647692f

// ---------------- packed f32x2 primitives (Blackwell FFMA2 path) ----------------
typedef unsigned long long f2;   // two packed fp32 lanes: {lo, hi}

__device__ __forceinline__ f2 f2pack(float a, float b) {
    f2 r; asm("mov.b64 %0, {%1, %2};" : "=l"(r) : "f"(a), "f"(b)); return r;
}
__device__ __forceinline__ void f2unpack(f2 v, float& a, float& b) {
    asm("mov.b64 {%0, %1}, %2;" : "=f"(a), "=f"(b) : "l"(v));
}
__device__ __forceinline__ f2 f2add(f2 a, f2 b) {
    f2 r; asm("add.rn.f32x2 %0, %1, %2;" : "=l"(r) : "l"(a), "l"(b)); return r;
}
__device__ __forceinline__ f2 f2mul(f2 a, f2 b) {
    f2 r; asm("mul.rn.f32x2 %0, %1, %2;" : "=l"(r) : "l"(a), "l"(b)); return r;
}
__device__ __forceinline__ f2 f2fma(f2 a, f2 b, f2 c) {
    f2 r; asm("fma.rn.f32x2 %0, %1, %2, %3;" : "=l"(r) : "l"(a), "l"(b), "l"(c)); return r;
}
__device__ __forceinline__ f2 f2splat(float s) { return f2pack(s, s); }

__device__ __forceinline__ f2 f2shfl_xor(f2 v, int m) {
    float a, b; f2unpack(v, a, b);
    a = __shfl_xor_sync(FULL_MASK, a, m);
    b = __shfl_xor_sync(FULL_MASK, b, m);
    return f2pack(a, b);
}

// Per-lane state for the packed warp-level 512-point FFT.
struct PTw {
    float twr[16], twi[16];        // four-step twiddles w512^{lane*brev4(p)} (scalar; splatted at use)
    f2 s16, s8, s4, s2, s1;        // packed ±1 per cross-lane stage
    f2 w16r, w16i, w8r, w8i, w4r, w4i, w2r, w2i;  // packed cross-lane stage twiddles
    f2 neg;                        // packed (-1, -1): sub/neg via fma
};

// Packed complex multiply by splatted twiddle: (ar,ai) *= (wr,wi)
__device__ __forceinline__ void f2cmul(f2& ar, f2& ai, f2 wr, f2 wi, f2 NEG) {
    f2 t1 = f2mul(ai, wi);
    f2 t2 = f2mul(ar, wr);
    f2 ni = f2fma(ai, wr, f2mul(ar, wi));
    ar = f2fma(t1, NEG, t2);       // ar*wr - ai*wi
    ai = ni;
}

// Two independent 512-point complex FFTs (lo-halves = FFT A, hi-halves = FFT B),
// computed simultaneously in packed f32x2 registers. Same scrambled (bit-reversed)
// output permutation for both — all the reduction needs.
__device__ __forceinline__ void fft512_p(f2 (&xr)[16], f2 (&xi)[16], const PTw& W)
{
    const f2 NEG = W.neg;
    const float C1 = 0.9238795325f, C2 = 0.7071067812f, C3 = 0.3826834324f;

    // ---- per-thread 16-point DIF FFT over register slots ----
    {   // span 8, twiddles w16^j
        const float WR[8] = {1.f,  C1,  C2,  C3, 0.f, -C3, -C2, -C1};
        const float WI[8] = {0.f, -C3, -C2, -C1, -1.f, -C1, -C2, -C3};
        #pragma unroll
        for (int j = 0; j < 8; ++j) {
            f2 ur = f2add(xr[j], xr[j+8]),        ui = f2add(xi[j], xi[j+8]);
            f2 vr = f2fma(xr[j+8], NEG, xr[j]),   vi = f2fma(xi[j+8], NEG, xi[j]);
            xr[j] = ur; xi[j] = ui;
            if (j == 0)      { xr[j+8] = vr;            xi[j+8] = vi; }
            else if (j == 4) { xr[j+8] = vi;            xi[j+8] = f2mul(vr, NEG); }   // * -i
            else {
                f2 wr = f2splat(WR[j]), wi = f2splat(WI[j]);
                f2 t1 = f2mul(vi, wi);
                xr[j+8] = f2fma(t1, NEG, f2mul(vr, wr));
                xi[j+8] = f2fma(vi, wr, f2mul(vr, wi));
            }
        }
    }
    {   // span 4, twiddles w8^j
        const float WR[4] = {1.f,  C2, 0.f, -C2};
        const float WI[4] = {0.f, -C2, -1.f, -C2};
        #pragma unroll
        for (int b = 0; b < 16; b += 8)
        #pragma unroll
        for (int j = 0; j < 4; ++j) {
            int p = b + j, q = p + 4;
            f2 ur = f2add(xr[p], xr[q]),        ui = f2add(xi[p], xi[q]);
            f2 vr = f2fma(xr[q], NEG, xr[p]),   vi = f2fma(xi[q], NEG, xi[p]);
            xr[p] = ur; xi[p] = ui;
            if (j == 0)      { xr[q] = vr; xi[q] = vi; }
            else if (j == 2) { xr[q] = vi; xi[q] = f2mul(vr, NEG); }   // * -i
            else {
                f2 wr = f2splat(WR[j]), wi = f2splat(WI[j]);
                f2 t1 = f2mul(vi, wi);
                xr[q] = f2fma(t1, NEG, f2mul(vr, wr));
                xi[q] = f2fma(vi, wr, f2mul(vr, wi));
            }
        }
    }
    // span 2, twiddles {1, -i}
    #pragma unroll
    for (int b = 0; b < 16; b += 4) {
        {
            int p = b, q = b + 2;
            f2 ur = f2add(xr[p], xr[q]),      ui = f2add(xi[p], xi[q]);
            f2 vr = f2fma(xr[q], NEG, xr[p]), vi = f2fma(xi[q], NEG, xi[p]);
            xr[p] = ur; xi[p] = ui; xr[q] = vr; xi[q] = vi;
        }
        {
            int p = b + 1, q = b + 3;
            f2 ur = f2add(xr[p], xr[q]),      ui = f2add(xi[p], xi[q]);
            f2 vr = f2fma(xr[q], NEG, xr[p]), vi = f2fma(xi[q], NEG, xi[p]);
            xr[p] = ur; xi[p] = ui;
            xr[q] = vi; xi[q] = f2mul(vr, NEG);   // * -i
        }
    }
    // span 1, twiddle 1
    #pragma unroll
    for (int b = 0; b < 16; b += 2) {
        f2 ur = f2add(xr[b], xr[b+1]),      ui = f2add(xi[b], xi[b+1]);
        f2 vr = f2fma(xr[b+1], NEG, xr[b]), vi = f2fma(xi[b+1], NEG, xi[b]);
        xr[b] = ur; xi[b] = ui; xr[b+1] = vr; xi[b+1] = vi;
    }

    // ---- four-step twiddle: slot p *= w512^{lane * brev4(p)} (splat scalar per site) ----
    #pragma unroll
    for (int p = 1; p < 16; ++p) {
        f2 wr = f2splat(W.twr[p]), wi = f2splat(W.twi[p]);
        f2cmul(xr[p], xi[p], wr, wi, NEG);
    }

    // ---- cross-lane 32-point DIF FFT per slot, stage-outer for shfl MLP ----
    {   // stage xor 16
        f2 s = W.s16, wr = W.w16r, wi = W.w16i;
        #pragma unroll
        for (int p = 0; p < 16; ++p) {
            f2 pr = f2shfl_xor(xr[p], 16), pi = f2shfl_xor(xi[p], 16);
            f2 ur = f2fma(xr[p], s, pr),   ui = f2fma(xi[p], s, pi);
            f2cmul(ur, ui, wr, wi, NEG);
            xr[p] = ur; xi[p] = ui;
        }
    }
    {   // stage xor 8
        f2 s = W.s8, wr = W.w8r, wi = W.w8i;
        #pragma unroll
        for (int p = 0; p < 16; ++p) {
            f2 pr = f2shfl_xor(xr[p], 8), pi = f2shfl_xor(xi[p], 8);
            f2 ur = f2fma(xr[p], s, pr),  ui = f2fma(xi[p], s, pi);
            f2cmul(ur, ui, wr, wi, NEG);
            xr[p] = ur; xi[p] = ui;
        }
    }
    {   // stage xor 4
        f2 s = W.s4, wr = W.w4r, wi = W.w4i;
        #pragma unroll
        for (int p = 0; p < 16; ++p) {
            f2 pr = f2shfl_xor(xr[p], 4), pi = f2shfl_xor(xi[p], 4);
            f2 ur = f2fma(xr[p], s, pr),  ui = f2fma(xi[p], s, pi);
            f2cmul(ur, ui, wr, wi, NEG);
            xr[p] = ur; xi[p] = ui;
        }
    }
    {   // stage xor 2
        f2 s = W.s2, wr = W.w2r, wi = W.w2i;
        #pragma unroll
        for (int p = 0; p < 16; ++p) {
            f2 pr = f2shfl_xor(xr[p], 2), pi = f2shfl_xor(xi[p], 2);
            f2 ur = f2fma(xr[p], s, pr),  ui = f2fma(xi[p], s, pi);
            f2cmul(ur, ui, wr, wi, NEG);
            xr[p] = ur; xi[p] = ui;
        }
    }
    {   // stage xor 1 (no twiddle)
        f2 s = W.s1;
        #pragma unroll
        for (int p = 0; p < 16; ++p) {
            f2 pr = f2shfl_xor(xr[p], 1), pi = f2shfl_xor(xi[p], 1);
            xr[p] = f2fma(xr[p], s, pr);
            xi[p] = f2fma(xi[p], s, pi);
        }
    }
}

// out[b] = Im( sum_f Z[f]^2 * conj(T[f]) ) / (2*D), Z = FFT(h+ir), T = FFT(t).
// Both FFTs packed into one f32x2 FFT: lo = Z-input, hi = T-input.
__global__ void __launch_bounds__(128, 3)
hole_kernel(const float* __restrict__ h, const float* __restrict__ r,
            const float* __restrict__ t, float* __restrict__ out, int nrows)
{
    const int lane   = threadIdx.x & 31;
    const int warp   = blockIdx.x * (blockDim.x >> 5) + (threadIdx.x >> 5);
    const int nwarps = gridDim.x * (blockDim.x >> 5);

    // ---- one-time per-lane twiddle setup ----
    PTw W;
    #pragma unroll
    for (int p = 0; p < 16; ++p) {
        int k1 = (int)(__brev((unsigned)p) >> 28);   // brev4(p)
        float ang = -(TWO_PI_F / 512.f) * (float)(lane * k1);
        sincosf(ang, &W.twi[p], &W.twr[p]);
    }
    W.s16 = f2splat((lane & 16) ? -1.f : 1.f);
    W.s8  = f2splat((lane & 8)  ? -1.f : 1.f);
    W.s4  = f2splat((lane & 4)  ? -1.f : 1.f);
    W.s2  = f2splat((lane & 2)  ? -1.f : 1.f);
    W.s1  = f2splat((lane & 1)  ? -1.f : 1.f);
    {
        float cr, ci;
        if (lane & 16) { float a = -(TWO_PI_F / 32.f) * (float)(lane & 15); sincosf(a, &ci, &cr); }
        else           { cr = 1.f; ci = 0.f; }
        W.w16r = f2splat(cr); W.w16i = f2splat(ci);
        if (lane & 8)  { float a = -(TWO_PI_F / 16.f) * (float)(lane & 7);  sincosf(a, &ci, &cr); }
        else           { cr = 1.f; ci = 0.f; }
        W.w8r = f2splat(cr); W.w8i = f2splat(ci);
        if (lane & 4)  { float a = -(TWO_PI_F / 8.f)  * (float)(lane & 3);  sincosf(a, &ci, &cr); }
        else           { cr = 1.f; ci = 0.f; }
        W.w4r = f2splat(cr); W.w4i = f2splat(ci);
        if (lane & 2)  { float a = -(TWO_PI_F / 4.f)  * (float)(lane & 1);  sincosf(a, &ci, &cr); }
        else           { cr = 1.f; ci = 0.f; }
        W.w2r = f2splat(cr); W.w2i = f2splat(ci);
    }
    W.neg = f2splat(-1.f);

    for (int row = warp; row < nrows; row += nwarps) {
        size_t base = (size_t)row * 512 + (size_t)lane;
        const float* hp = h + base;
        const float* rp = r + base;
        const float* tp = t + base;

        // coalesced loads; pack lo = Z-FFT input (h + i r), hi = T-FFT input (t + i*0)
        f2 xr[16], xi[16];
        #pragma unroll
        for (int s = 0; s < 16; ++s) {
            float hv = hp[32 * s];
            float tv = tp[32 * s];
            float rv = rp[32 * s];
            xr[s] = f2pack(hv, tv);
            xi[s] = f2pack(rv, 0.f);
        }

        fft512_p(xr, xi, W);

        // acc = sum over this lane's 16 frequencies of Im(Z^2 * conj(T))
        float acc = 0.f;
        #pragma unroll
        for (int s = 0; s < 16; ++s) {
            float a, tr, b, ti;
            f2unpack(xr[s], a, tr);    // lo = Re Z, hi = Re T
            f2unpack(xi[s], b, ti);    // lo = Im Z, hi = Im T
            float im2 = 2.f * a * b;               // Im(Z^2)
            float re2 = a * a - b * b;             // Re(Z^2)
            acc = fmaf(im2, tr, acc);
            acc = fmaf(-re2, ti, acc);
        }
        #pragma unroll
        for (int o = 16; o; o >>= 1)
            acc += __shfl_xor_sync(FULL_MASK, acc, o);

        if (lane == 0) out[row] = acc * (1.f / 1024.f);   // 1/(2*D)
    }
}

extern "C" void kernel_launch(void* const* d_in, const int* in_sizes, int n_in,
                              void* d_out, int out_size)
{
    const float* h = (const float*)d_in[0];
    const float* r = (const float*)d_in[1];
    const float* t = (const float*)d_in[2];
    float* out = (float*)d_out;

    int nrows = in_sizes[0] / 512;      // 131072

    const int threads = 128;            // 4 warps/block
    const int blocks  = 4096;           // 16384 warps -> 8 rows per warp
    hole_kernel<<<blocks, threads>>>(h, r, t, out, nrows);
}

// round 3
// speedup vs baseline: 1.4518x; 1.2679x over previous
#include <cuda_runtime.h>
#include <math.h>

#define FULL_MASK 0xffffffffu
#define TWO_PI_F 6.28318530717958647692f

// ---------------- packed f32x2 primitives ----------------
typedef unsigned long long f2;   // two packed fp32 lanes: {lo, hi}

__device__ __forceinline__ f2 f2pack(float a, float b) {
    f2 r; asm("mov.b64 %0, {%1, %2};" : "=l"(r) : "f"(a), "f"(b)); return r;
}
__device__ __forceinline__ void f2unpack(f2 v, float& a, float& b) {
    asm("mov.b64 {%0, %1}, %2;" : "=f"(a), "=f"(b) : "l"(v));
}
__device__ __forceinline__ f2 f2add(f2 a, f2 b) {
    f2 r; asm("add.rn.f32x2 %0, %1, %2;" : "=l"(r) : "l"(a), "l"(b)); return r;
}
__device__ __forceinline__ f2 f2mul(f2 a, f2 b) {
    f2 r; asm("mul.rn.f32x2 %0, %1, %2;" : "=l"(r) : "l"(a), "l"(b)); return r;
}
__device__ __forceinline__ f2 f2fma(f2 a, f2 b, f2 c) {
    f2 r; asm("fma.rn.f32x2 %0, %1, %2, %3;" : "=l"(r) : "l"(a), "l"(b), "l"(c)); return r;
}
__device__ __forceinline__ f2 f2splat(float s) { return f2pack(s, s); }

__device__ __forceinline__ f2 f2shfl_xor(f2 v, int m) {
    float a, b; f2unpack(v, a, b);
    a = __shfl_xor_sync(FULL_MASK, a, m);
    b = __shfl_xor_sync(FULL_MASK, b, m);
    return f2pack(a, b);
}

__device__ __forceinline__ constexpr int brev4c(int p) {
    return ((p & 1) << 3) | ((p & 2) << 1) | ((p & 4) >> 1) | ((p & 8) >> 3);
}

// Per-thread 16-point DIF FFT over the 16 register slots (packed: 2 FFTs at once).
// Input: slot s = time index n. Output: slot p holds bin brev4(p).
// All twiddles are compile-time constants.
__device__ __forceinline__ void fft16_regs(f2 (&xr)[16], f2 (&xi)[16], f2 NEG)
{
    const float C1 = 0.9238795325f, C2 = 0.7071067812f, C3 = 0.3826834324f;
    {   // span 8, twiddles w16^j
        const float WR[8] = {1.f,  C1,  C2,  C3, 0.f, -C3, -C2, -C1};
        const float WI[8] = {0.f, -C3, -C2, -C1, -1.f, -C1, -C2, -C3};
        #pragma unroll
        for (int j = 0; j < 8; ++j) {
            f2 ur = f2add(xr[j], xr[j+8]),        ui = f2add(xi[j], xi[j+8]);
            f2 vr = f2fma(xr[j+8], NEG, xr[j]),   vi = f2fma(xi[j+8], NEG, xi[j]);
            xr[j] = ur; xi[j] = ui;
            if (j == 0)      { xr[j+8] = vr;  xi[j+8] = vi; }
            else if (j == 4) { xr[j+8] = vi;  xi[j+8] = f2mul(vr, NEG); }     // * -i
            else {
                f2 wr = f2splat(WR[j]), wi = f2splat(WI[j]);
                f2 t1 = f2mul(vi, wi);
                xr[j+8] = f2fma(t1, NEG, f2mul(vr, wr));
                xi[j+8] = f2fma(vi, wr, f2mul(vr, wi));
            }
        }
    }
    {   // span 4, twiddles w8^j
        const float WR[4] = {1.f,  C2, 0.f, -C2};
        const float WI[4] = {0.f, -C2, -1.f, -C2};
        #pragma unroll
        for (int b = 0; b < 16; b += 8)
        #pragma unroll
        for (int j = 0; j < 4; ++j) {
            int p = b + j, q = p + 4;
            f2 ur = f2add(xr[p], xr[q]),        ui = f2add(xi[p], xi[q]);
            f2 vr = f2fma(xr[q], NEG, xr[p]),   vi = f2fma(xi[q], NEG, xi[p]);
            xr[p] = ur; xi[p] = ui;
            if (j == 0)      { xr[q] = vr; xi[q] = vi; }
            else if (j == 2) { xr[q] = vi; xi[q] = f2mul(vr, NEG); }          // * -i
            else {
                f2 wr = f2splat(WR[j]), wi = f2splat(WI[j]);
                f2 t1 = f2mul(vi, wi);
                xr[q] = f2fma(t1, NEG, f2mul(vr, wr));
                xi[q] = f2fma(vi, wr, f2mul(vr, wi));
            }
        }
    }
    // span 2, twiddles {1, -i}
    #pragma unroll
    for (int b = 0; b < 16; b += 4) {
        {
            int p = b, q = b + 2;
            f2 ur = f2add(xr[p], xr[q]),      ui = f2add(xi[p], xi[q]);
            f2 vr = f2fma(xr[q], NEG, xr[p]), vi = f2fma(xi[q], NEG, xi[p]);
            xr[p] = ur; xi[p] = ui; xr[q] = vr; xi[q] = vi;
        }
        {
            int p = b + 1, q = b + 3;
            f2 ur = f2add(xr[p], xr[q]),      ui = f2add(xi[p], xi[q]);
            f2 vr = f2fma(xr[q], NEG, xr[p]), vi = f2fma(xi[q], NEG, xi[p]);
            xr[p] = ur; xi[p] = ui;
            xr[q] = vi; xi[q] = f2mul(vr, NEG);   // * -i
        }
    }
    // span 1
    #pragma unroll
    for (int b = 0; b < 16; b += 2) {
        f2 ur = f2add(xr[b], xr[b+1]),      ui = f2add(xi[b], xi[b+1]);
        f2 vr = f2fma(xr[b+1], NEG, xr[b]), vi = f2fma(xi[b+1], NEG, xi[b]);
        xr[b] = ur; xi[b] = ui; xr[b+1] = vr; xi[b+1] = vi;
    }
}

// out[b] = Im( sum_f Z[f]^2 * conj(T[f]) ) / (2*D), Z = FFT(h+ir), T = FFT(t).
// 512 = 16 (regs) x 16 (regs after smem transpose) x 2 (one shfl stage).
__global__ void __launch_bounds__(128, 3)
hole_kernel(const float* __restrict__ h, const float* __restrict__ r,
            const float* __restrict__ t, float* __restrict__ out, int nrows)
{
    const int lane = threadIdx.x & 31;
    const int wid  = threadIdx.x >> 5;
    const int warp = blockIdx.x * 4 + wid;
    const int nwarps = gridDim.x * 4;

    // warp-private transpose slabs: [16 k1 rows][33 m cols] (pad 33 -> conflict-free)
    __shared__ f2 smre[4][16 * 33];
    __shared__ f2 smim[4][16 * 33];
    f2* __restrict__ sre = smre[wid];
    f2* __restrict__ sim = smim[wid];

    // ---- per-lane setup ----
    // four-step twiddles w512^{lane * brev4(p)} (scalar; splatted at use)
    float twr[16], twi[16];
    #pragma unroll
    for (int p = 0; p < 16; ++p) {
        int k1 = brev4c(p);
        float ang = -(TWO_PI_F / 512.f) * (float)(lane * k1);
        sincosf(ang, &twi[p], &twr[p]);
    }
    const f2 NEG = f2splat(-1.f);
    const f2 S16 = f2splat((lane & 16) ? -1.f : 1.f);   // final-stage sign (n3)
    const bool up = (lane & 16) != 0;                   // n3 == 1 lanes
    const int  rb = (lane & 15) * 33 + (lane >> 4);     // read base: k1*33 + n3

    // w32^{k2} table, k2 in [0,16): w = exp(-2*pi*i*k2/32)
    const float W32R[16] = {
        1.f, 0.98078528f, 0.92387953f, 0.83146961f, 0.70710678f, 0.55557023f,
        0.38268343f, 0.19509032f, 0.f, -0.19509032f, -0.38268343f, -0.55557023f,
        -0.70710678f, -0.83146961f, -0.92387953f, -0.98078528f };
    const float W32I[16] = {
        0.f, -0.19509032f, -0.38268343f, -0.55557023f, -0.70710678f, -0.83146961f,
        -0.92387953f, -0.98078528f, -1.f, -0.98078528f, -0.92387953f, -0.83146961f,
        -0.70710678f, -0.55557023f, -0.38268343f, -0.19509032f };

    for (int row = warp; row < nrows; row += nwarps) {
        size_t base = (size_t)row * 512 + (size_t)lane;
        const float* hp = h + base;
        const float* rp = r + base;
        const float* tp = t + base;

        // coalesced loads; lo lane = Z-FFT input (h + i r), hi = T-FFT input (t)
        f2 xr[16], xi[16];
        #pragma unroll
        for (int s = 0; s < 16; ++s) {
            float hv = hp[32 * s];
            float tv = tp[32 * s];
            float rv = rp[32 * s];
            xr[s] = f2pack(hv, tv);
            xi[s] = f2pack(rv, 0.f);
        }

        // ---- pass 1: 16-pt FFT over slots (n1) ----
        fft16_regs(xr, xi, NEG);

        // ---- four-step twiddle: slot p *= w512^{lane * brev4(p)} ----
        #pragma unroll
        for (int p = 1; p < 16; ++p) {
            f2 wr = f2splat(twr[p]), wi = f2splat(twi[p]);
            f2 t1 = f2mul(xi[p], wi);
            f2 ni = f2fma(xi[p], wr, f2mul(xr[p], wi));
            xr[p] = f2fma(t1, NEG, f2mul(xr[p], wr));
            xi[p] = ni;
        }

        // ---- transpose via warp-private smem: [k1][m] ----
        __syncwarp();
        #pragma unroll
        for (int p = 0; p < 16; ++p) {
            int k1 = brev4c(p);
            sre[k1 * 33 + lane] = xr[p];
            sim[k1 * 33 + lane] = xi[p];
        }
        __syncwarp();
        // lane' = 16*n3 + k1 reads f[n2] = y[k1][2*n2 + n3]
        #pragma unroll
        for (int s = 0; s < 16; ++s) {
            xr[s] = sre[rb + 2 * s];
            xi[s] = sim[rb + 2 * s];
        }

        // ---- pass 2: 16-pt FFT over n2 ----
        fft16_regs(xr, xi, NEG);

        // ---- w32^{k2*n3} twiddle + final cross-lane radix-2 over n3 ----
        #pragma unroll
        for (int p = 0; p < 16; ++p) {
            const int k2 = brev4c(p);
            if (k2 != 0) {
                float cr = up ? W32R[k2] : 1.f;     // FSEL (alu pipe)
                float ci = up ? W32I[k2] : 0.f;
                f2 wr = f2splat(cr), wi = f2splat(ci);
                f2 t1 = f2mul(xi[p], wi);
                f2 ni = f2fma(xi[p], wr, f2mul(xr[p], wi));
                xr[p] = f2fma(t1, NEG, f2mul(xr[p], wr));
                xi[p] = ni;
            }
            f2 pr = f2shfl_xor(xr[p], 16);
            f2 pi = f2shfl_xor(xi[p], 16);
            xr[p] = f2fma(xr[p], S16, pr);
            xi[p] = f2fma(xi[p], S16, pi);
        }

        // ---- reduction: acc = sum_f Im(Z^2 * conj(T)) over this lane's 16 bins ----
        float acc = 0.f;
        #pragma unroll
        for (int s = 0; s < 16; ++s) {
            float a, tr, b, ti;
            f2unpack(xr[s], a, tr);    // lo = Re Z, hi = Re T
            f2unpack(xi[s], b, ti);    // lo = Im Z, hi = Im T
            float im2 = 2.f * a * b;               // Im(Z^2)
            float re2 = a * a - b * b;             // Re(Z^2)
            acc = fmaf(im2, tr, acc);
            acc = fmaf(-re2, ti, acc);
        }
        #pragma unroll
        for (int o = 16; o; o >>= 1)
            acc += __shfl_xor_sync(FULL_MASK, acc, o);

        if (lane == 0) out[row] = acc * (1.f / 1024.f);   // 1/(2*D)
    }
}

extern "C" void kernel_launch(void* const* d_in, const int* in_sizes, int n_in,
                              void* d_out, int out_size)
{
    const float* h = (const float*)d_in[0];
    const float* r = (const float*)d_in[1];
    const float* t = (const float*)d_in[2];
    float* out = (float*)d_out;

    int nrows = in_sizes[0] / 512;      // 131072

    const int threads = 128;            // 4 warps/block
    const int blocks  = 4096;           // 16384 warps -> 8 rows per warp
    hole_kernel<<<blocks, threads>>>(h, r, t, out, nrows);
}

// round 4
// speedup vs baseline: 1.6000x; 1.1020x over previous
#include <cuda_runtime.h>
#include <math.h>

#define FULL_MASK 0xffffffffu
#define TWO_PI_F 6.28318530717958647692f

// ---------------- packed f32x2 primitives ----------------
typedef unsigned long long f2;   // two packed fp32 lanes: {lo, hi}

__device__ __forceinline__ f2 f2pack(float a, float b) {
    f2 r; asm("mov.b64 %0, {%1, %2};" : "=l"(r) : "f"(a), "f"(b)); return r;
}
__device__ __forceinline__ void f2unpack(f2 v, float& a, float& b) {
    asm("mov.b64 {%0, %1}, %2;" : "=f"(a), "=f"(b) : "l"(v));
}
__device__ __forceinline__ f2 f2add(f2 a, f2 b) {
    f2 r; asm("add.rn.f32x2 %0, %1, %2;" : "=l"(r) : "l"(a), "l"(b)); return r;
}
__device__ __forceinline__ f2 f2mul(f2 a, f2 b) {
    f2 r; asm("mul.rn.f32x2 %0, %1, %2;" : "=l"(r) : "l"(a), "l"(b)); return r;
}
__device__ __forceinline__ f2 f2fma(f2 a, f2 b, f2 c) {
    f2 r; asm("fma.rn.f32x2 %0, %1, %2, %3;" : "=l"(r) : "l"(a), "l"(b), "l"(c)); return r;
}
__device__ __forceinline__ f2 f2splat(float s) { return f2pack(s, s); }

__device__ __forceinline__ f2 f2shfl_xor(f2 v, int m) {
    float a, b; f2unpack(v, a, b);
    a = __shfl_xor_sync(FULL_MASK, a, m);
    b = __shfl_xor_sync(FULL_MASK, b, m);
    return f2pack(a, b);
}

__device__ __forceinline__ constexpr int brev4c(int p) {
    return ((p & 1) << 3) | ((p & 2) << 1) | ((p & 4) >> 1) | ((p & 8) >> 3);
}

// Per-thread 16-point DIF FFT over the 16 register slots (packed: 2 FFTs at once).
// Input: slot s = time index n. Output: slot p holds bin brev4(p).
// All twiddles are compile-time constants.
__device__ __forceinline__ void fft16_regs(f2 (&xr)[16], f2 (&xi)[16], f2 NEG)
{
    const float C1 = 0.9238795325f, C2 = 0.7071067812f, C3 = 0.3826834324f;
    {   // span 8, twiddles w16^j
        const float WR[8] = {1.f,  C1,  C2,  C3, 0.f, -C3, -C2, -C1};
        const float WI[8] = {0.f, -C3, -C2, -C1, -1.f, -C1, -C2, -C3};
        #pragma unroll
        for (int j = 0; j < 8; ++j) {
            f2 ur = f2add(xr[j], xr[j+8]),        ui = f2add(xi[j], xi[j+8]);
            f2 vr = f2fma(xr[j+8], NEG, xr[j]),   vi = f2fma(xi[j+8], NEG, xi[j]);
            xr[j] = ur; xi[j] = ui;
            if (j == 0)      { xr[j+8] = vr;  xi[j+8] = vi; }
            else if (j == 4) { xr[j+8] = vi;  xi[j+8] = f2mul(vr, NEG); }     // * -i
            else {
                f2 wr = f2splat(WR[j]), wi = f2splat(WI[j]);
                f2 t1 = f2mul(vi, wi);
                xr[j+8] = f2fma(t1, NEG, f2mul(vr, wr));
                xi[j+8] = f2fma(vi, wr, f2mul(vr, wi));
            }
        }
    }
    {   // span 4, twiddles w8^j
        const float WR[4] = {1.f,  C2, 0.f, -C2};
        const float WI[4] = {0.f, -C2, -1.f, -C2};
        #pragma unroll
        for (int b = 0; b < 16; b += 8)
        #pragma unroll
        for (int j = 0; j < 4; ++j) {
            int p = b + j, q = p + 4;
            f2 ur = f2add(xr[p], xr[q]),        ui = f2add(xi[p], xi[q]);
            f2 vr = f2fma(xr[q], NEG, xr[p]),   vi = f2fma(xi[q], NEG, xi[p]);
            xr[p] = ur; xi[p] = ui;
            if (j == 0)      { xr[q] = vr; xi[q] = vi; }
            else if (j == 2) { xr[q] = vi; xi[q] = f2mul(vr, NEG); }          // * -i
            else {
                f2 wr = f2splat(WR[j]), wi = f2splat(WI[j]);
                f2 t1 = f2mul(vi, wi);
                xr[q] = f2fma(t1, NEG, f2mul(vr, wr));
                xi[q] = f2fma(vi, wr, f2mul(vr, wi));
            }
        }
    }
    // span 2, twiddles {1, -i}
    #pragma unroll
    for (int b = 0; b < 16; b += 4) {
        {
            int p = b, q = b + 2;
            f2 ur = f2add(xr[p], xr[q]),      ui = f2add(xi[p], xi[q]);
            f2 vr = f2fma(xr[q], NEG, xr[p]), vi = f2fma(xi[q], NEG, xi[p]);
            xr[p] = ur; xi[p] = ui; xr[q] = vr; xi[q] = vi;
        }
        {
            int p = b + 1, q = b + 3;
            f2 ur = f2add(xr[p], xr[q]),      ui = f2add(xi[p], xi[q]);
            f2 vr = f2fma(xr[q], NEG, xr[p]), vi = f2fma(xi[q], NEG, xi[p]);
            xr[p] = ur; xi[p] = ui;
            xr[q] = vi; xi[q] = f2mul(vr, NEG);   // * -i
        }
    }
    // span 1
    #pragma unroll
    for (int b = 0; b < 16; b += 2) {
        f2 ur = f2add(xr[b], xr[b+1]),      ui = f2add(xi[b], xi[b+1]);
        f2 vr = f2fma(xr[b+1], NEG, xr[b]), vi = f2fma(xi[b+1], NEG, xi[b]);
        xr[b] = ur; xi[b] = ui; xr[b+1] = vr; xi[b+1] = vi;
    }
}

// out[b] = Im( sum_f Z[f]^2 * conj(T[f]) ) / (2*D), Z = FFT(h+ir), T = FFT(t).
// 512 = 16 (regs) x 16 (regs after smem transpose) x 2 (one shfl stage).
__global__ void __launch_bounds__(128, 4)
hole_kernel(const float* __restrict__ h, const float* __restrict__ r,
            const float* __restrict__ t, float* __restrict__ out, int nrows)
{
    const int lane = threadIdx.x & 31;
    const int wid  = threadIdx.x >> 5;
    const int warp = blockIdx.x * 4 + wid;
    const int nwarps = gridDim.x * 4;

    // warp-private transpose slabs: [16 k1 rows][33 m cols] (pad 33 -> conflict-free)
    __shared__ f2 smre[4][16 * 33];
    __shared__ f2 smim[4][16 * 33];
    // shared four-step twiddle table: tw512[p][lane] = w512^{lane * brev4(p)}
    // (identical for all warps; frees ~32 registers per thread)
    __shared__ float2 tw512[16][32];

    f2* __restrict__ sre = smre[wid];
    f2* __restrict__ sim = smim[wid];

    // ---- one-time per-block twiddle table init ----
    for (int e = threadIdx.x; e < 512; e += 128) {
        int p  = e >> 5;
        int ln = e & 31;
        int k1 = brev4c(p);
        float ang = -(TWO_PI_F / 512.f) * (float)(ln * k1);
        float s, c;
        sincosf(ang, &s, &c);
        tw512[p][ln] = make_float2(c, s);
    }
    __syncthreads();

    // ---- per-lane constants ----
    const f2 NEG = f2splat(-1.f);
    const f2 S16 = f2splat((lane & 16) ? -1.f : 1.f);   // final-stage sign (n3)
    const bool up = (lane & 16) != 0;                   // n3 == 1 lanes
    const int  rb = (lane & 15) * 33 + (lane >> 4);     // read base: k1*33 + n3

    // w32^{k2} table, k2 in [0,16): w = exp(-2*pi*i*k2/32)  (compile-time selected)
    const float W32R[16] = {
        1.f, 0.98078528f, 0.92387953f, 0.83146961f, 0.70710678f, 0.55557023f,
        0.38268343f, 0.19509032f, 0.f, -0.19509032f, -0.38268343f, -0.55557023f,
        -0.70710678f, -0.83146961f, -0.92387953f, -0.98078528f };
    const float W32I[16] = {
        0.f, -0.19509032f, -0.38268343f, -0.55557023f, -0.70710678f, -0.83146961f,
        -0.92387953f, -0.98078528f, -1.f, -0.98078528f, -0.92387953f, -0.83146961f,
        -0.70710678f, -0.55557023f, -0.38268343f, -0.19509032f };

    for (int row = warp; row < nrows; row += nwarps) {
        size_t base = (size_t)row * 512 + (size_t)lane;
        const float* hp = h + base;
        const float* rp = r + base;
        const float* tp = t + base;

        // coalesced loads; lo lane = Z-FFT input (h + i r), hi = T-FFT input (t)
        f2 xr[16], xi[16];
        #pragma unroll
        for (int s = 0; s < 16; ++s) {
            float hv = hp[32 * s];
            float tv = tp[32 * s];
            float rv = rp[32 * s];
            xr[s] = f2pack(hv, tv);
            xi[s] = f2pack(rv, 0.f);
        }

        // ---- pass 1: 16-pt FFT over slots (n1) ----
        fft16_regs(xr, xi, NEG);

        // ---- four-step twiddle: slot p *= w512^{lane * brev4(p)} (from smem) ----
        #pragma unroll
        for (int p = 1; p < 16; ++p) {
            float2 w = tw512[p][lane];
            f2 wr = f2splat(w.x), wi = f2splat(w.y);
            f2 t1 = f2mul(xi[p], wi);
            f2 ni = f2fma(xi[p], wr, f2mul(xr[p], wi));
            xr[p] = f2fma(t1, NEG, f2mul(xr[p], wr));
            xi[p] = ni;
        }

        // ---- transpose via warp-private smem: [k1][m] ----
        __syncwarp();
        #pragma unroll
        for (int p = 0; p < 16; ++p) {
            int k1 = brev4c(p);
            sre[k1 * 33 + lane] = xr[p];
            sim[k1 * 33 + lane] = xi[p];
        }
        __syncwarp();
        // lane' = 16*n3 + k1 reads f[n2] = y[k1][2*n2 + n3]
        #pragma unroll
        for (int s = 0; s < 16; ++s) {
            xr[s] = sre[rb + 2 * s];
            xi[s] = sim[rb + 2 * s];
        }

        // ---- pass 2: 16-pt FFT over n2 ----
        fft16_regs(xr, xi, NEG);

        // ---- w32^{k2*n3} twiddle + final cross-lane radix-2 over n3 ----
        #pragma unroll
        for (int p = 0; p < 16; ++p) {
            const int k2 = brev4c(p);
            if (k2 != 0) {
                float cr = up ? W32R[k2] : 1.f;     // FSEL (alu pipe)
                float ci = up ? W32I[k2] : 0.f;
                f2 wr = f2splat(cr), wi = f2splat(ci);
                f2 t1 = f2mul(xi[p], wi);
                f2 ni = f2fma(xi[p], wr, f2mul(xr[p], wi));
                xr[p] = f2fma(t1, NEG, f2mul(xr[p], wr));
                xi[p] = ni;
            }
            f2 pr = f2shfl_xor(xr[p], 16);
            f2 pi = f2shfl_xor(xi[p], 16);
            xr[p] = f2fma(xr[p], S16, pr);
            xi[p] = f2fma(xi[p], S16, pi);
        }

        // ---- reduction: acc = sum_f Im(Z^2 * conj(T)) over this lane's 16 bins ----
        float acc = 0.f;
        #pragma unroll
        for (int s = 0; s < 16; ++s) {
            float a, tr, b, ti;
            f2unpack(xr[s], a, tr);    // lo = Re Z, hi = Re T
            f2unpack(xi[s], b, ti);    // lo = Im Z, hi = Im T
            float im2 = 2.f * a * b;               // Im(Z^2)
            float re2 = a * a - b * b;             // Re(Z^2)
            acc = fmaf(im2, tr, acc);
            acc = fmaf(-re2, ti, acc);
        }
        #pragma unroll
        for (int o = 16; o; o >>= 1)
            acc += __shfl_xor_sync(FULL_MASK, acc, o);

        if (lane == 0) out[row] = acc * (1.f / 1024.f);   // 1/(2*D)
    }
}

extern "C" void kernel_launch(void* const* d_in, const int* in_sizes, int n_in,
                              void* d_out, int out_size)
{
    const float* h = (const float*)d_in[0];
    const float* r = (const float*)d_in[1];
    const float* t = (const float*)d_in[2];
    float* out = (float*)d_out;

    int nrows = in_sizes[0] / 512;      // 131072

    const int threads = 128;            // 4 warps/block
    const int blocks  = 4096;           // 16384 warps -> 8 rows per warp
    hole_kernel<<<blocks, threads>>>(h, r, t, out, nrows);
}